// round 13
// baseline (speedup 1.0000x reference)
#include <cuda_runtime.h>

#define B_   256
#define R_   1152
#define C_   10
#define IC_  8
#define OC_  16
#define RT_  16
#define CHUNKS_ (R_/RT_)   /* 72 */
#define NG_   (B_*C_*OC_)  /* 40960 */

// Scratch (static device memory — no allocations).
__device__ __align__(16) float g_Vsum[NG_];             // running sum of v_j
__device__ __align__(16) float g_scratch[CHUNKS_*NG_];  // per-r-chunk partial s

// ---- packed fp32x2 helpers (Blackwell FFMA2 — only reachable via PTX) ------
typedef unsigned long long u64t;
__device__ __forceinline__ u64t fma2(u64t a, u64t b, u64t c) {
    u64t d;
    asm("fma.rn.f32x2 %0, %1, %2, %3;" : "=l"(d) : "l"(a), "l"(b), "l"(c));
    return d;
}
__device__ __forceinline__ u64t mul2(u64t a, u64t b) {
    u64t d;
    asm("mul.rn.f32x2 %0, %1, %2;" : "=l"(d) : "l"(a), "l"(b));
    return d;
}
__device__ __forceinline__ u64t bcast2(float x) {
    u64t d; unsigned int u = __float_as_uint(x);
    asm("mov.b64 %0, {%1, %1};" : "=l"(d) : "r"(u));
    return d;
}
__device__ __forceinline__ float2 unpack2(u64t v) {
    unsigned int lo, hi;
    asm("mov.b64 {%0, %1}, %2;" : "=r"(lo), "=r"(hi) : "l"(v));
    return make_float2(__uint_as_float(lo), __uint_as_float(hi));
}

// W smem tile: original layout [RT_][C_][IC_][OC_] floats = 80 KB.
// As ulonglong2 (16B): index ((r*C_ + c)*IC_ + i)*4 + oq  -> the 4 floats of
// o-quarter oq. A warp has 8 b-groups x 4 oq lanes: 4 unique 16B addresses
// spanning one 64B run -> minimal wavefronts.
#define SMEM_BYTES_ (RT_*C_*IC_*OC_*4)   /* 81920 */

__device__ __forceinline__ void load_w_tile(float4* Ws, const float* w,
                                            int chunk, int tid) {
    const float4* wsrc = reinterpret_cast<const float4*>(w)
                       + (size_t)chunk * (RT_*C_*IC_*4);
    #pragma unroll
    for (int k = 0; k < (RT_*C_*IC_*4)/256; ++k) Ws[k*256 + tid] = wsrc[k*256 + tid];
}

// ---------------------------------------------------------------------------
// First routing pass (uniform coupling 0.1): osplit=4, nb=1, f32x2, ~70 regs.
// Grid (CHUNKS_, 4), block 256, 2 CTAs/SM. Thread -> (b = by*64 + tid>>2, oq).
// ---------------------------------------------------------------------------
__global__ __launch_bounds__(256, 2)
void pass_first(const float* __restrict__ x, const float* __restrict__ w) {
    extern __shared__ __align__(16) float4 Ws[];
    const int tid   = threadIdx.x;
    const int chunk = blockIdx.x;
    const int r0    = chunk * RT_;
    const int oq    = tid & 3;
    const int b     = blockIdx.y * 64 + (tid >> 2);

    load_w_tile(Ws, w, chunk, tid);
    __syncthreads();

    u64t s2[C_][2];
    #pragma unroll
    for (int c = 0; c < C_; ++c) { s2[c][0] = 0ull; s2[c][1] = 0ull; }

    const float* xrow = x + ((size_t)b * R_ + r0) * IC_;

    #pragma unroll 1
    for (int r = 0; r < RT_; ++r) {
        float4 xa = *reinterpret_cast<const float4*>(xrow + r*IC_);
        float4 xb = *reinterpret_cast<const float4*>(xrow + r*IC_ + 4);
        u64t x2[8];
        x2[0]=bcast2(xa.x); x2[1]=bcast2(xa.y); x2[2]=bcast2(xa.z); x2[3]=bcast2(xa.w);
        x2[4]=bcast2(xb.x); x2[5]=bcast2(xb.y); x2[6]=bcast2(xb.z); x2[7]=bcast2(xb.w);

        const ulonglong2* wr2 =
            reinterpret_cast<const ulonglong2*>(Ws) + (size_t)r * (C_*IC_*4) + oq;
        #pragma unroll
        for (int c = 0; c < C_; ++c) {
            #pragma unroll
            for (int i = 0; i < IC_; ++i) {
                ulonglong2 q = wr2[(c*IC_ + i)*4];        // LDS.128
                s2[c][0] = fma2(x2[i], q.x, s2[c][0]);
                s2[c][1] = fma2(x2[i], q.y, s2[c][1]);
            }
        }
    }

    const u64t tenth = bcast2(0.1f);
    u64t* dst = reinterpret_cast<u64t*>(
        g_scratch + ((size_t)chunk*B_ + b)*(C_*OC_) + oq*4);
    #pragma unroll
    for (int c = 0; c < C_; ++c) {
        dst[c*8]     = mul2(s2[c][0], tenth);
        dst[c*8 + 1] = mul2(s2[c][1], tenth);
    }
}

// ---------------------------------------------------------------------------
// Routing iteration pass: osplit=4, nb=1, f32x2, target ~120 regs (no spill).
// Grid (CHUNKS_, 4), block 256, 2 CTAs/SM -> 4 warps/SMSP.
// Thread -> (b = by*64 + tid>>2, oq = tid&3).
// ---------------------------------------------------------------------------
__global__ __launch_bounds__(256, 2)
void pass_iter(const float* __restrict__ x, const float* __restrict__ w) {
    extern __shared__ __align__(16) float4 Ws[];
    const int tid   = threadIdx.x;
    const int chunk = blockIdx.x;
    const int r0    = chunk * RT_;
    const int oq    = tid & 3;
    const int b     = blockIdx.y * 64 + (tid >> 2);

    load_w_tile(Ws, w, chunk, tid);
    __syncthreads();

    u64t s2[C_][2];
    #pragma unroll
    for (int c = 0; c < C_; ++c) { s2[c][0] = 0ull; s2[c][1] = 0ull; }

    const float* xrow = x + ((size_t)b * R_ + r0) * IC_;
    // Vsum for this (b, o-quarter): one ulonglong2 (16B) per c, L1-resident.
    // Stride per c is OC_=16 floats = 4 ulonglong2.
    const ulonglong2* vsp =
        reinterpret_cast<const ulonglong2*>(g_Vsum + b*(C_*OC_) + oq*4);

    #pragma unroll 1
    for (int r = 0; r < RT_; ++r) {
        float4 xa = *reinterpret_cast<const float4*>(xrow + r*IC_);
        float4 xb = *reinterpret_cast<const float4*>(xrow + r*IC_ + 4);
        u64t x2[8];
        x2[0]=bcast2(xa.x); x2[1]=bcast2(xa.y); x2[2]=bcast2(xa.z); x2[3]=bcast2(xa.w);
        x2[4]=bcast2(xb.x); x2[5]=bcast2(xb.y); x2[6]=bcast2(xb.z); x2[7]=bcast2(xb.w);

        const ulonglong2* wr2 =
            reinterpret_cast<const ulonglong2*>(Ws) + (size_t)r * (C_*IC_*4) + oq;

        u64t u2[C_][2];
        float t[C_];
        #pragma unroll
        for (int c = 0; c < C_; ++c) {
            u64t a0 = 0ull, a1 = 0ull;
            #pragma unroll
            for (int i = 0; i < IC_; ++i) {
                ulonglong2 q = wr2[(c*IC_ + i)*4];        // LDS.128
                a0 = fma2(x2[i], q.x, a0);
                a1 = fma2(x2[i], q.y, a1);
            }
            u2[c][0] = a0; u2[c][1] = a1;
            ulonglong2 vq = vsp[c*4];                     // LDG.128, L1-hit (FIXED)
            u64t t2 = fma2(a1, vq.y, mul2(a0, vq.x));
            float2 tp = unpack2(t2);
            t[c] = tp.x + tp.y;                           // partial (this oq)
        }

        // complete t over the 4 o-quarter lanes (same b)
        #pragma unroll
        for (int c = 0; c < C_; ++c) {
            t[c] += __shfl_xor_sync(0xffffffffu, t[c], 1);
            t[c] += __shfl_xor_sync(0xffffffffu, t[c], 2);
        }
        float m = t[0];
        #pragma unroll
        for (int c = 1; c < C_; ++c) m = fmaxf(m, t[c]);
        float z = 0.0f;
        #pragma unroll
        for (int c = 0; c < C_; ++c) { t[c] = __expf(t[c] - m); z += t[c]; }
        float inv = __fdividef(1.0f, z);

        #pragma unroll
        for (int c = 0; c < C_; ++c) {
            u64t cc2 = bcast2(t[c] * inv);
            s2[c][0] = fma2(cc2, u2[c][0], s2[c][0]);
            s2[c][1] = fma2(cc2, u2[c][1], s2[c][1]);
        }
    }

    u64t* dst = reinterpret_cast<u64t*>(
        g_scratch + ((size_t)chunk*B_ + b)*(C_*OC_) + oq*4);
    #pragma unroll
    for (int c = 0; c < C_; ++c) {
        dst[c*8]     = s2[c][0];
        dst[c*8 + 1] = s2[c][1];
    }
}

// ---------------------------------------------------------------------------
// Reduce 72 partials, squash, update Vsum / emit output.
// Block 256 = 32 g-float4 x 8 k-slices, smem combine, 4-lane shfl. Grid 320.
// ---------------------------------------------------------------------------
template<bool FIRSTV, bool LAST>
__global__ __launch_bounds__(256, 4)
void squash_kernel(float* __restrict__ out) {
    const int tid = threadIdx.x;
    const int ks  = tid >> 5;          // 0..7
    const int gl  = tid & 31;          // 0..31
    const int g4  = blockIdx.x * 32 + gl;   // float4 index into [NG_/4]

    const float4* src = reinterpret_cast<const float4*>(g_scratch);
    float4 a = make_float4(0.f, 0.f, 0.f, 0.f);
    #pragma unroll
    for (int k = 0; k < CHUNKS_/8; ++k) {
        float4 tv = src[(size_t)(ks * (CHUNKS_/8) + k) * (NG_/4) + g4];
        a.x += tv.x; a.y += tv.y; a.z += tv.z; a.w += tv.w;
    }

    __shared__ float4 red[8][32];
    red[ks][gl] = a;
    __syncthreads();

    if (tid < 32) {
        float4 s = red[0][tid];
        #pragma unroll
        for (int j = 1; j < 8; ++j) {
            float4 t = red[j][tid];
            s.x += t.x; s.y += t.y; s.z += t.z; s.w += t.w;
        }
        float sq = s.x*s.x + s.y*s.y + s.z*s.z + s.w*s.w;
        sq += __shfl_xor_sync(0xffffffffu, sq, 1);      // 4 float4 lanes = one
        sq += __shfl_xor_sync(0xffffffffu, sq, 2);      // (b,c) 16-vector
        float n = sqrtf(sq);
        float sc = (sq / (1.0f + sq)) / (n + 1e-8f);
        float4 v = make_float4(s.x*sc, s.y*sc, s.z*sc, s.w*sc);
        int g = blockIdx.x * 32 + tid;
        if (LAST) {
            reinterpret_cast<float4*>(out)[g] = v;
        } else if (FIRSTV) {
            reinterpret_cast<float4*>(g_Vsum)[g] = v;
        } else {
            float4 o = reinterpret_cast<float4*>(g_Vsum)[g];
            o.x += v.x; o.y += v.y; o.z += v.z; o.w += v.w;
            reinterpret_cast<float4*>(g_Vsum)[g] = o;
        }
    }
}

extern "C" void kernel_launch(void* const* d_in, const int* in_sizes, int n_in,
                              void* d_out, int out_size) {
    const float* x = (const float*)d_in[0];
    const float* w = (const float*)d_in[1];
    float* out = (float*)d_out;

    cudaFuncSetAttribute(pass_first, cudaFuncAttributeMaxDynamicSharedMemorySize, SMEM_BYTES_);
    cudaFuncSetAttribute(pass_iter,  cudaFuncAttributeMaxDynamicSharedMemorySize, SMEM_BYTES_);

    dim3 grid(CHUNKS_, 4);   // 288 CTAs, 64 batches each, 2 CTAs/SM

    pass_first<<<grid, 256, SMEM_BYTES_>>>(x, w);    // iter 1 (uniform coupling)
    squash_kernel<true,  false><<<320, 256>>>(out);  // v1, Vsum = v1
    pass_iter<<<grid, 256, SMEM_BYTES_>>>(x, w);     // iter 2
    squash_kernel<false, false><<<320, 256>>>(out);  // v2, Vsum = v1+v2
    pass_iter<<<grid, 256, SMEM_BYTES_>>>(x, w);     // iter 3
    squash_kernel<false, true ><<<320, 256>>>(out);  // v3 -> output
}

// round 14
// speedup vs baseline: 1.3522x; 1.3522x over previous
#include <cuda_runtime.h>

#define B_   256
#define R_   1152
#define C_   10
#define IC_  8
#define OC_  16
#define RT_  16
#define CHUNKS_ (R_/RT_)   /* 72 */
#define NG_   (B_*C_*OC_)  /* 40960 */

// Scratch (static device memory — no allocations).
__device__ __align__(16) float g_Vsum[NG_];             // running sum of v_j
__device__ __align__(16) float g_scratch[CHUNKS_*NG_];  // per-r-chunk partial s

// ---- packed fp32x2 helpers (Blackwell FFMA2 — only reachable via PTX) ------
typedef unsigned long long u64t;
__device__ __forceinline__ u64t fma2(u64t a, u64t b, u64t c) {
    u64t d;
    asm("fma.rn.f32x2 %0, %1, %2, %3;" : "=l"(d) : "l"(a), "l"(b), "l"(c));
    return d;
}
__device__ __forceinline__ u64t mul2(u64t a, u64t b) {
    u64t d;
    asm("mul.rn.f32x2 %0, %1, %2;" : "=l"(d) : "l"(a), "l"(b));
    return d;
}
__device__ __forceinline__ u64t bcast2(float x) {
    u64t d; unsigned int u = __float_as_uint(x);
    asm("mov.b64 %0, {%1, %1};" : "=l"(d) : "r"(u));
    return d;
}
__device__ __forceinline__ float2 unpack2(u64t v) {
    unsigned int lo, hi;
    asm("mov.b64 {%0, %1}, %2;" : "=r"(lo), "=r"(hi) : "l"(v));
    return make_float2(__uint_as_float(lo), __uint_as_float(hi));
}

#define SMEM_BYTES_ (RT_*C_*IC_*OC_*4)   /* 81920 */

__device__ __forceinline__ void load_w_tile(float4* Ws, const float* w,
                                            int chunk, int tid) {
    const float4* wsrc = reinterpret_cast<const float4*>(w)
                       + (size_t)chunk * (RT_*C_*IC_*4);
    #pragma unroll
    for (int k = 0; k < (RT_*C_*IC_*4)/256; ++k) Ws[k*256 + tid] = wsrc[k*256 + tid];
}

// ---------------------------------------------------------------------------
// First routing pass (uniform coupling 0.1): nb=2, osplit=4, packed f32x2.
// Grid (CHUNKS_, 2), block 256. Thread -> (batch pair, o-quarter).
// (R6 version — known good.)
// ---------------------------------------------------------------------------
__global__ __launch_bounds__(256, 1)
void pass_first(const float* __restrict__ x, const float* __restrict__ w) {
    extern __shared__ __align__(16) float4 Ws[];
    const int tid   = threadIdx.x;
    const int chunk = blockIdx.x;
    const int r0    = chunk * RT_;
    const int oq    = tid & 3;
    const int b0    = blockIdx.y * 128 + (tid >> 2) * 2;

    load_w_tile(Ws, w, chunk, tid);
    __syncthreads();

    u64t s0[C_][2], s1[C_][2];
    #pragma unroll
    for (int c = 0; c < C_; ++c) {
        s0[c][0] = 0ull; s0[c][1] = 0ull;
        s1[c][0] = 0ull; s1[c][1] = 0ull;
    }

    const float* xrow0 = x + ((size_t)b0       * R_ + r0) * IC_;
    const float* xrow1 = x + ((size_t)(b0 + 1) * R_ + r0) * IC_;

    #pragma unroll 1
    for (int r = 0; r < RT_; ++r) {
        float4 xa = *reinterpret_cast<const float4*>(xrow0 + r*IC_);
        float4 xb = *reinterpret_cast<const float4*>(xrow0 + r*IC_ + 4);
        float4 ya = *reinterpret_cast<const float4*>(xrow1 + r*IC_);
        float4 yb = *reinterpret_cast<const float4*>(xrow1 + r*IC_ + 4);
        u64t x2[8], y2[8];
        x2[0]=bcast2(xa.x); x2[1]=bcast2(xa.y); x2[2]=bcast2(xa.z); x2[3]=bcast2(xa.w);
        x2[4]=bcast2(xb.x); x2[5]=bcast2(xb.y); x2[6]=bcast2(xb.z); x2[7]=bcast2(xb.w);
        y2[0]=bcast2(ya.x); y2[1]=bcast2(ya.y); y2[2]=bcast2(ya.z); y2[3]=bcast2(ya.w);
        y2[4]=bcast2(yb.x); y2[5]=bcast2(yb.y); y2[6]=bcast2(yb.z); y2[7]=bcast2(yb.w);

        const ulonglong2* wr2 =
            reinterpret_cast<const ulonglong2*>(Ws) + (size_t)r * (C_*IC_*4) + oq;
        #pragma unroll
        for (int c = 0; c < C_; ++c) {
            #pragma unroll
            for (int i = 0; i < IC_; ++i) {
                ulonglong2 q = wr2[(c*IC_ + i)*4];        // 16B smem broadcast
                s0[c][0] = fma2(x2[i], q.x, s0[c][0]);
                s0[c][1] = fma2(x2[i], q.y, s0[c][1]);
                s1[c][0] = fma2(y2[i], q.x, s1[c][0]);
                s1[c][1] = fma2(y2[i], q.y, s1[c][1]);
            }
        }
    }

    const u64t tenth = bcast2(0.1f);
    u64t* d0 = reinterpret_cast<u64t*>(g_scratch + ((size_t)chunk*B_ +  b0     )*(C_*OC_) + oq*4);
    u64t* d1 = reinterpret_cast<u64t*>(g_scratch + ((size_t)chunk*B_ + (b0 + 1))*(C_*OC_) + oq*4);
    #pragma unroll
    for (int c = 0; c < C_; ++c) {
        d0[c*8]     = mul2(s0[c][0], tenth);
        d0[c*8 + 1] = mul2(s0[c][1], tenth);
        d1[c*8]     = mul2(s1[c][0], tenth);
        d1[c*8 + 1] = mul2(s1[c][1], tenth);
    }
}

// ---------------------------------------------------------------------------
// Routing iteration pass: nb=1, osplit=2, f32x2, TWO-ROUTE INTERLEAVE.
// Grid (CHUNKS_, 2), block 256. Thread -> (b = by*128 + tid>>1, oh = tid&1).
// Routes processed in pairs: two independent u/t/softmax chains overlap the
// serial softmax tail; Vsum loads shared between the pair; shfl inside the
// c-loop so its latency hides under the next c's accumulation.
// ---------------------------------------------------------------------------
__global__ __launch_bounds__(256, 1)
void pass_iter(const float* __restrict__ x, const float* __restrict__ w) {
    extern __shared__ __align__(16) float4 Ws[];
    const int tid   = threadIdx.x;
    const int chunk = blockIdx.x;
    const int r0    = chunk * RT_;
    const int oh    = tid & 1;
    const int b     = blockIdx.y * 128 + (tid >> 1);

    load_w_tile(Ws, w, chunk, tid);
    __syncthreads();

    u64t s2[C_][4];
    #pragma unroll
    for (int c = 0; c < C_; ++c)
        #pragma unroll
        for (int j = 0; j < 4; ++j) s2[c][j] = 0ull;

    const float* xrow = x + ((size_t)b * R_ + r0) * IC_;
    const ulonglong2* vs2 =
        reinterpret_cast<const ulonglong2*>(g_Vsum + b * (C_*OC_) + oh * 8);

    #pragma unroll 1
    for (int rr = 0; rr < RT_/2; ++rr) {
        const int r = rr * 2;
        // x for both routes of the pair
        float4 xa = *reinterpret_cast<const float4*>(xrow + r*IC_);
        float4 xb = *reinterpret_cast<const float4*>(xrow + r*IC_ + 4);
        float4 yc = *reinterpret_cast<const float4*>(xrow + (r+1)*IC_);
        float4 yd = *reinterpret_cast<const float4*>(xrow + (r+1)*IC_ + 4);
        u64t xA[8], xB[8];
        xA[0]=bcast2(xa.x); xA[1]=bcast2(xa.y); xA[2]=bcast2(xa.z); xA[3]=bcast2(xa.w);
        xA[4]=bcast2(xb.x); xA[5]=bcast2(xb.y); xA[6]=bcast2(xb.z); xA[7]=bcast2(xb.w);
        xB[0]=bcast2(yc.x); xB[1]=bcast2(yc.y); xB[2]=bcast2(yc.z); xB[3]=bcast2(yc.w);
        xB[4]=bcast2(yd.x); xB[5]=bcast2(yd.y); xB[6]=bcast2(yd.z); xB[7]=bcast2(yd.w);

        const ulonglong2* wrA =
            reinterpret_cast<const ulonglong2*>(Ws) + (size_t)r * (C_*IC_*4) + oh*2;
        const ulonglong2* wrB = wrA + (C_*IC_*4);

        u64t uA[C_][4], uB[C_][4];
        float tA[C_], tB[C_];
        #pragma unroll
        for (int c = 0; c < C_; ++c) {
            u64t a0=0ull, a1=0ull, a2=0ull, a3=0ull;
            u64t d0=0ull, d1=0ull, d2=0ull, d3=0ull;
            #pragma unroll
            for (int i = 0; i < IC_; ++i) {
                ulonglong2 pA = wrA[(c*IC_ + i)*4];
                ulonglong2 qA = wrA[(c*IC_ + i)*4 + 1];
                ulonglong2 pB = wrB[(c*IC_ + i)*4];
                ulonglong2 qB = wrB[(c*IC_ + i)*4 + 1];
                a0 = fma2(xA[i], pA.x, a0);
                a1 = fma2(xA[i], pA.y, a1);
                a2 = fma2(xA[i], qA.x, a2);
                a3 = fma2(xA[i], qA.y, a3);
                d0 = fma2(xB[i], pB.x, d0);
                d1 = fma2(xB[i], pB.y, d1);
                d2 = fma2(xB[i], qB.x, d2);
                d3 = fma2(xB[i], qB.y, d3);
            }
            uA[c][0]=a0; uA[c][1]=a1; uA[c][2]=a2; uA[c][3]=a3;
            uB[c][0]=d0; uB[c][1]=d1; uB[c][2]=d2; uB[c][3]=d3;
            // Vsum shared between the two routes (same b, same oh)
            ulonglong2 vA = vs2[c*4];
            ulonglong2 vB = vs2[c*4 + 1];
            u64t tpA = mul2(a0, vA.x);
            tpA = fma2(a1, vA.y, tpA);
            tpA = fma2(a2, vB.x, tpA);
            tpA = fma2(a3, vB.y, tpA);
            u64t tpB = mul2(d0, vA.x);
            tpB = fma2(d1, vA.y, tpB);
            tpB = fma2(d2, vB.x, tpB);
            tpB = fma2(d3, vB.y, tpB);
            float2 fa = unpack2(tpA);
            float2 fb = unpack2(tpB);
            float ta = fa.x + fa.y;
            float tb = fb.x + fb.y;
            // partner-lane completion INSIDE the loop: latency overlaps next c
            tA[c] = ta + __shfl_xor_sync(0xffffffffu, ta, 1);
            tB[c] = tb + __shfl_xor_sync(0xffffffffu, tb, 1);
        }

        // softmax over c for both routes (tree max, depth 4)
        float mA = fmaxf(fmaxf(fmaxf(tA[0],tA[1]), fmaxf(tA[2],tA[3])),
                         fmaxf(fmaxf(tA[4],tA[5]), fmaxf(tA[6],tA[7])));
        mA = fmaxf(mA, fmaxf(tA[8],tA[9]));
        float mB = fmaxf(fmaxf(fmaxf(tB[0],tB[1]), fmaxf(tB[2],tB[3])),
                         fmaxf(fmaxf(tB[4],tB[5]), fmaxf(tB[6],tB[7])));
        mB = fmaxf(mB, fmaxf(tB[8],tB[9]));
        float zA = 0.0f, zB = 0.0f;
        #pragma unroll
        for (int c = 0; c < C_; ++c) {
            tA[c] = __expf(tA[c] - mA); zA += tA[c];
            tB[c] = __expf(tB[c] - mB); zB += tB[c];
        }
        float invA = __fdividef(1.0f, zA);
        float invB = __fdividef(1.0f, zB);

        #pragma unroll
        for (int c = 0; c < C_; ++c) {
            u64t cA = bcast2(tA[c] * invA);
            u64t cB = bcast2(tB[c] * invB);
            s2[c][0] = fma2(cA, uA[c][0], s2[c][0]);
            s2[c][1] = fma2(cA, uA[c][1], s2[c][1]);
            s2[c][2] = fma2(cA, uA[c][2], s2[c][2]);
            s2[c][3] = fma2(cA, uA[c][3], s2[c][3]);
            s2[c][0] = fma2(cB, uB[c][0], s2[c][0]);
            s2[c][1] = fma2(cB, uB[c][1], s2[c][1]);
            s2[c][2] = fma2(cB, uB[c][2], s2[c][2]);
            s2[c][3] = fma2(cB, uB[c][3], s2[c][3]);
        }
    }

    u64t* dst = reinterpret_cast<u64t*>(
        g_scratch + ((size_t)chunk*B_ + b)*(C_*OC_) + oh*8);
    #pragma unroll
    for (int c = 0; c < C_; ++c) {
        dst[c*8]     = s2[c][0];
        dst[c*8 + 1] = s2[c][1];
        dst[c*8 + 2] = s2[c][2];
        dst[c*8 + 3] = s2[c][3];
    }
}

// ---------------------------------------------------------------------------
// Reduce 72 partials, squash, update Vsum / emit output.
// Block 256 = 32 g-float4 x 8 k-slices, smem combine, 4-lane shfl. Grid 320.
// ---------------------------------------------------------------------------
template<bool FIRSTV, bool LAST>
__global__ __launch_bounds__(256, 4)
void squash_kernel(float* __restrict__ out) {
    const int tid = threadIdx.x;
    const int ks  = tid >> 5;          // 0..7
    const int gl  = tid & 31;          // 0..31
    const int g4  = blockIdx.x * 32 + gl;   // float4 index into [NG_/4]

    const float4* src = reinterpret_cast<const float4*>(g_scratch);
    float4 a = make_float4(0.f, 0.f, 0.f, 0.f);
    #pragma unroll
    for (int k = 0; k < CHUNKS_/8; ++k) {
        float4 tv = src[(size_t)(ks * (CHUNKS_/8) + k) * (NG_/4) + g4];
        a.x += tv.x; a.y += tv.y; a.z += tv.z; a.w += tv.w;
    }

    __shared__ float4 red[8][32];
    red[ks][gl] = a;
    __syncthreads();

    if (tid < 32) {
        float4 s = red[0][tid];
        #pragma unroll
        for (int j = 1; j < 8; ++j) {
            float4 t = red[j][tid];
            s.x += t.x; s.y += t.y; s.z += t.z; s.w += t.w;
        }
        float sq = s.x*s.x + s.y*s.y + s.z*s.z + s.w*s.w;
        sq += __shfl_xor_sync(0xffffffffu, sq, 1);      // 4 float4 lanes = one
        sq += __shfl_xor_sync(0xffffffffu, sq, 2);      // (b,c) 16-vector
        float n = sqrtf(sq);
        float sc = (sq / (1.0f + sq)) / (n + 1e-8f);
        float4 v = make_float4(s.x*sc, s.y*sc, s.z*sc, s.w*sc);
        int g = blockIdx.x * 32 + tid;
        if (LAST) {
            reinterpret_cast<float4*>(out)[g] = v;
        } else if (FIRSTV) {
            reinterpret_cast<float4*>(g_Vsum)[g] = v;
        } else {
            float4 o = reinterpret_cast<float4*>(g_Vsum)[g];
            o.x += v.x; o.y += v.y; o.z += v.z; o.w += v.w;
            reinterpret_cast<float4*>(g_Vsum)[g] = o;
        }
    }
}

extern "C" void kernel_launch(void* const* d_in, const int* in_sizes, int n_in,
                              void* d_out, int out_size) {
    const float* x = (const float*)d_in[0];
    const float* w = (const float*)d_in[1];
    float* out = (float*)d_out;

    cudaFuncSetAttribute(pass_first, cudaFuncAttributeMaxDynamicSharedMemorySize, SMEM_BYTES_);
    cudaFuncSetAttribute(pass_iter,  cudaFuncAttributeMaxDynamicSharedMemorySize, SMEM_BYTES_);

    dim3 grid(CHUNKS_, 2);   // 144 CTAs, 1 per SM

    pass_first<<<grid, 256, SMEM_BYTES_>>>(x, w);    // iter 1 (uniform coupling)
    squash_kernel<true,  false><<<320, 256>>>(out);  // v1, Vsum = v1
    pass_iter<<<grid, 256, SMEM_BYTES_>>>(x, w);     // iter 2
    squash_kernel<false, false><<<320, 256>>>(out);  // v2, Vsum = v1+v2
    pass_iter<<<grid, 256, SMEM_BYTES_>>>(x, w);     // iter 3
    squash_kernel<false, true ><<<320, 256>>>(out);  // v3 -> output
}

// round 16
// speedup vs baseline: 1.5719x; 1.1625x over previous
#include <cuda_runtime.h>

#define B_   256
#define R_   1152
#define C_   10
#define IC_  8
#define OC_  16
#define RT_  16
#define CHUNKS_ (R_/RT_)   /* 72 */
#define NG_   (B_*C_*OC_)  /* 40960 */

// Scratch (static device memory — no allocations).
__device__ __align__(16) float g_Vsum[NG_];             // running sum of v_j
__device__ __align__(16) float g_scratch[CHUNKS_*NG_];  // per-r-chunk partial s

// ---- packed fp32x2 helpers (Blackwell FFMA2 — only reachable via PTX) ------
typedef unsigned long long u64t;
__device__ __forceinline__ u64t fma2(u64t a, u64t b, u64t c) {
    u64t d;
    asm("fma.rn.f32x2 %0, %1, %2, %3;" : "=l"(d) : "l"(a), "l"(b), "l"(c));
    return d;
}
__device__ __forceinline__ u64t mul2(u64t a, u64t b) {
    u64t d;
    asm("mul.rn.f32x2 %0, %1, %2;" : "=l"(d) : "l"(a), "l"(b));
    return d;
}
__device__ __forceinline__ u64t bcast2(float x) {
    u64t d; unsigned int u = __float_as_uint(x);
    asm("mov.b64 %0, {%1, %1};" : "=l"(d) : "r"(u));
    return d;
}
__device__ __forceinline__ float2 unpack2(u64t v) {
    unsigned int lo, hi;
    asm("mov.b64 {%0, %1}, %2;" : "=r"(lo), "=r"(hi) : "l"(v));
    return make_float2(__uint_as_float(lo), __uint_as_float(hi));
}

#define SMEM_BYTES_ (RT_*C_*IC_*OC_*4)   /* 81920 */

__device__ __forceinline__ void load_w_tile(float4* Ws, const float* w,
                                            int chunk, int tid) {
    const float4* wsrc = reinterpret_cast<const float4*>(w)
                       + (size_t)chunk * (RT_*C_*IC_*4);
    #pragma unroll
    for (int k = 0; k < (RT_*C_*IC_*4)/256; ++k) Ws[k*256 + tid] = wsrc[k*256 + tid];
}

// ---------------------------------------------------------------------------
// First routing pass (uniform coupling 0.1): nb=2, osplit=4, packed f32x2.
// Grid (CHUNKS_, 2), block 256. Thread -> (batch pair, o-quarter).
// (R6 version — measured good.)
// ---------------------------------------------------------------------------
__global__ __launch_bounds__(256, 1)
void pass_first(const float* __restrict__ x, const float* __restrict__ w) {
    extern __shared__ __align__(16) float4 Ws[];
    const int tid   = threadIdx.x;
    const int chunk = blockIdx.x;
    const int r0    = chunk * RT_;
    const int oq    = tid & 3;
    const int b0    = blockIdx.y * 128 + (tid >> 2) * 2;

    load_w_tile(Ws, w, chunk, tid);
    __syncthreads();

    u64t s0[C_][2], s1[C_][2];
    #pragma unroll
    for (int c = 0; c < C_; ++c) {
        s0[c][0] = 0ull; s0[c][1] = 0ull;
        s1[c][0] = 0ull; s1[c][1] = 0ull;
    }

    const float* xrow0 = x + ((size_t)b0       * R_ + r0) * IC_;
    const float* xrow1 = x + ((size_t)(b0 + 1) * R_ + r0) * IC_;

    #pragma unroll 1
    for (int r = 0; r < RT_; ++r) {
        float4 xa = *reinterpret_cast<const float4*>(xrow0 + r*IC_);
        float4 xb = *reinterpret_cast<const float4*>(xrow0 + r*IC_ + 4);
        float4 ya = *reinterpret_cast<const float4*>(xrow1 + r*IC_);
        float4 yb = *reinterpret_cast<const float4*>(xrow1 + r*IC_ + 4);
        u64t x2[8], y2[8];
        x2[0]=bcast2(xa.x); x2[1]=bcast2(xa.y); x2[2]=bcast2(xa.z); x2[3]=bcast2(xa.w);
        x2[4]=bcast2(xb.x); x2[5]=bcast2(xb.y); x2[6]=bcast2(xb.z); x2[7]=bcast2(xb.w);
        y2[0]=bcast2(ya.x); y2[1]=bcast2(ya.y); y2[2]=bcast2(ya.z); y2[3]=bcast2(ya.w);
        y2[4]=bcast2(yb.x); y2[5]=bcast2(yb.y); y2[6]=bcast2(yb.z); y2[7]=bcast2(yb.w);

        const ulonglong2* wr2 =
            reinterpret_cast<const ulonglong2*>(Ws) + (size_t)r * (C_*IC_*4) + oq;
        #pragma unroll
        for (int c = 0; c < C_; ++c) {
            #pragma unroll
            for (int i = 0; i < IC_; ++i) {
                ulonglong2 q = wr2[(c*IC_ + i)*4];        // 16B smem broadcast
                s0[c][0] = fma2(x2[i], q.x, s0[c][0]);
                s0[c][1] = fma2(x2[i], q.y, s0[c][1]);
                s1[c][0] = fma2(y2[i], q.x, s1[c][0]);
                s1[c][1] = fma2(y2[i], q.y, s1[c][1]);
            }
        }
    }

    const u64t tenth = bcast2(0.1f);
    u64t* d0 = reinterpret_cast<u64t*>(g_scratch + ((size_t)chunk*B_ +  b0     )*(C_*OC_) + oq*4);
    u64t* d1 = reinterpret_cast<u64t*>(g_scratch + ((size_t)chunk*B_ + (b0 + 1))*(C_*OC_) + oq*4);
    #pragma unroll
    for (int c = 0; c < C_; ++c) {
        d0[c*8]     = mul2(s0[c][0], tenth);
        d0[c*8 + 1] = mul2(s0[c][1], tenth);
        d1[c*8]     = mul2(s1[c][0], tenth);
        d1[c*8 + 1] = mul2(s1[c][1], tenth);
    }
}

// ---------------------------------------------------------------------------
// Routing iteration pass: nb=1, osplit=2, f32x2 (R6 shape) with tail surgery:
//   - Vsum hoisted to registers (loaded once, not 160 LDGs in-loop)
//   - partner-shfl inside the c-loop (latency overlaps next c's FMAs)
//   - tree max instead of 9-deep serial chain
// Grid (CHUNKS_, 2), block 256. Thread -> (b = by*128 + tid>>1, oh = tid&1).
// ---------------------------------------------------------------------------
__global__ __launch_bounds__(256, 1)
void pass_iter(const float* __restrict__ x, const float* __restrict__ w) {
    extern __shared__ __align__(16) float4 Ws[];
    const int tid   = threadIdx.x;
    const int chunk = blockIdx.x;
    const int r0    = chunk * RT_;
    const int oh    = tid & 1;
    const int b     = blockIdx.y * 128 + (tid >> 1);

    load_w_tile(Ws, w, chunk, tid);

    // Hoist Vsum for this (b, o-half): 10c x 2 ulonglong2 = 40 regs, loaded once.
    const ulonglong2* vsp =
        reinterpret_cast<const ulonglong2*>(g_Vsum + b * (C_*OC_) + oh * 8);
    ulonglong2 vsA[C_], vsB[C_];
    #pragma unroll
    for (int c = 0; c < C_; ++c) { vsA[c] = vsp[c*4]; vsB[c] = vsp[c*4 + 1]; }

    __syncthreads();

    u64t s2[C_][4];
    #pragma unroll
    for (int c = 0; c < C_; ++c)
        #pragma unroll
        for (int j = 0; j < 4; ++j) s2[c][j] = 0ull;

    const float* xrow = x + ((size_t)b * R_ + r0) * IC_;

    #pragma unroll 1
    for (int r = 0; r < RT_; ++r) {
        float4 xa = *reinterpret_cast<const float4*>(xrow + r*IC_);
        float4 xb = *reinterpret_cast<const float4*>(xrow + r*IC_ + 4);
        u64t x2[8];
        x2[0]=bcast2(xa.x); x2[1]=bcast2(xa.y); x2[2]=bcast2(xa.z); x2[3]=bcast2(xa.w);
        x2[4]=bcast2(xb.x); x2[5]=bcast2(xb.y); x2[6]=bcast2(xb.z); x2[7]=bcast2(xb.w);

        const ulonglong2* wr2 =
            reinterpret_cast<const ulonglong2*>(Ws) + (size_t)r * (C_*IC_*4) + oh*2;

        u64t u2[C_][4];
        float t[C_];
        #pragma unroll
        for (int c = 0; c < C_; ++c) {
            u64t a0 = 0ull, a1 = 0ull, a2 = 0ull, a3 = 0ull;
            #pragma unroll
            for (int i = 0; i < IC_; ++i) {
                ulonglong2 pA = wr2[(c*IC_ + i)*4];
                ulonglong2 pB = wr2[(c*IC_ + i)*4 + 1];
                a0 = fma2(x2[i], pA.x, a0);
                a1 = fma2(x2[i], pA.y, a1);
                a2 = fma2(x2[i], pB.x, a2);
                a3 = fma2(x2[i], pB.y, a3);
            }
            u2[c][0]=a0; u2[c][1]=a1; u2[c][2]=a2; u2[c][3]=a3;
            // t partial from register-resident Vsum (no memory ops)
            u64t t2 = mul2(a0, vsA[c].x);
            t2 = fma2(a1, vsA[c].y, t2);
            t2 = fma2(a2, vsB[c].x, t2);
            t2 = fma2(a3, vsB[c].y, t2);
            float2 tp = unpack2(t2);
            float ta = tp.x + tp.y;
            // partner-lane completion INSIDE the loop: overlaps next c's FMAs
            t[c] = ta + __shfl_xor_sync(0xffffffffu, ta, 1);
        }

        // softmax over c (tree max, depth 4)
        float m = fmaxf(fmaxf(fmaxf(t[0],t[1]), fmaxf(t[2],t[3])),
                        fmaxf(fmaxf(t[4],t[5]), fmaxf(t[6],t[7])));
        m = fmaxf(m, fmaxf(t[8],t[9]));
        float z = 0.0f;
        #pragma unroll
        for (int c = 0; c < C_; ++c) { t[c] = __expf(t[c] - m); z += t[c]; }
        float inv = __fdividef(1.0f, z);

        #pragma unroll
        for (int c = 0; c < C_; ++c) {
            u64t cc2 = bcast2(t[c] * inv);
            s2[c][0] = fma2(cc2, u2[c][0], s2[c][0]);
            s2[c][1] = fma2(cc2, u2[c][1], s2[c][1]);
            s2[c][2] = fma2(cc2, u2[c][2], s2[c][2]);
            s2[c][3] = fma2(cc2, u2[c][3], s2[c][3]);
        }
    }

    u64t* dst = reinterpret_cast<u64t*>(
        g_scratch + ((size_t)chunk*B_ + b)*(C_*OC_) + oh*8);
    #pragma unroll
    for (int c = 0; c < C_; ++c) {
        dst[c*8]     = s2[c][0];
        dst[c*8 + 1] = s2[c][1];
        dst[c*8 + 2] = s2[c][2];
        dst[c*8 + 3] = s2[c][3];
    }
}

// ---------------------------------------------------------------------------
// Reduce 72 partials, squash, update Vsum / emit output.
// Block 256 = 32 g-float4 x 8 k-slices, smem combine, 4-lane shfl. Grid 320.
// ---------------------------------------------------------------------------
template<bool FIRSTV, bool LAST>
__global__ __launch_bounds__(256, 4)
void squash_kernel(float* __restrict__ out) {
    const int tid = threadIdx.x;
    const int ks  = tid >> 5;          // 0..7
    const int gl  = tid & 31;          // 0..31
    const int g4  = blockIdx.x * 32 + gl;   // float4 index into [NG_/4]

    const float4* src = reinterpret_cast<const float4*>(g_scratch);
    float4 a = make_float4(0.f, 0.f, 0.f, 0.f);
    #pragma unroll
    for (int k = 0; k < CHUNKS_/8; ++k) {
        float4 tv = src[(size_t)(ks * (CHUNKS_/8) + k) * (NG_/4) + g4];
        a.x += tv.x; a.y += tv.y; a.z += tv.z; a.w += tv.w;
    }

    __shared__ float4 red[8][32];
    red[ks][gl] = a;
    __syncthreads();

    if (tid < 32) {
        float4 s = red[0][tid];
        #pragma unroll
        for (int j = 1; j < 8; ++j) {
            float4 t = red[j][tid];
            s.x += t.x; s.y += t.y; s.z += t.z; s.w += t.w;
        }
        float sq = s.x*s.x + s.y*s.y + s.z*s.z + s.w*s.w;
        sq += __shfl_xor_sync(0xffffffffu, sq, 1);      // 4 float4 lanes = one
        sq += __shfl_xor_sync(0xffffffffu, sq, 2);      // (b,c) 16-vector
        float n = sqrtf(sq);
        float sc = (sq / (1.0f + sq)) / (n + 1e-8f);
        float4 v = make_float4(s.x*sc, s.y*sc, s.z*sc, s.w*sc);
        int g = blockIdx.x * 32 + tid;
        if (LAST) {
            reinterpret_cast<float4*>(out)[g] = v;
        } else if (FIRSTV) {
            reinterpret_cast<float4*>(g_Vsum)[g] = v;
        } else {
            float4 o = reinterpret_cast<float4*>(g_Vsum)[g];
            o.x += v.x; o.y += v.y; o.z += v.z; o.w += v.w;
            reinterpret_cast<float4*>(g_Vsum)[g] = o;
        }
    }
}

extern "C" void kernel_launch(void* const* d_in, const int* in_sizes, int n_in,
                              void* d_out, int out_size) {
    const float* x = (const float*)d_in[0];
    const float* w = (const float*)d_in[1];
    float* out = (float*)d_out;

    cudaFuncSetAttribute(pass_first, cudaFuncAttributeMaxDynamicSharedMemorySize, SMEM_BYTES_);
    cudaFuncSetAttribute(pass_iter,  cudaFuncAttributeMaxDynamicSharedMemorySize, SMEM_BYTES_);

    dim3 grid(CHUNKS_, 2);   // 144 CTAs, 1 per SM

    pass_first<<<grid, 256, SMEM_BYTES_>>>(x, w);    // iter 1 (uniform coupling)
    squash_kernel<true,  false><<<320, 256>>>(out);  // v1, Vsum = v1
    pass_iter<<<grid, 256, SMEM_BYTES_>>>(x, w);     // iter 2
    squash_kernel<false, false><<<320, 256>>>(out);  // v2, Vsum = v1+v2
    pass_iter<<<grid, 256, SMEM_BYTES_>>>(x, w);     // iter 3
    squash_kernel<false, true ><<<320, 256>>>(out);  // v3 -> output
}